// round 1
// baseline (speedup 1.0000x reference)
#include <cuda_runtime.h>

// out = (1-lam)^(T-1) * adj[0] + sum_{t=1..T-1} lam*(1-lam)^(T-1-t) * adj[t]
// Pure HBM-streaming weighted sum. float4 vectorized, MLP=16.

template <int T>
__global__ void __launch_bounds__(256)
ema_fold_kernel(const float4* __restrict__ adj,
                const float* __restrict__ lam_p,
                float4* __restrict__ out,
                int n4) {
    int i = blockIdx.x * blockDim.x + threadIdx.x;
    if (i >= n4) return;

    const float lam = __ldg(lam_p);
    const float om  = 1.0f - lam;

    // Weights: w[t] = lam * om^(T-1-t) for t>=1, w[0] = om^(T-1)
    float w[T];
    float p = 1.0f;
#pragma unroll
    for (int t = T - 1; t >= 1; --t) { w[t] = lam * p; p *= om; }
    w[0] = p;

    float4 s = make_float4(0.f, 0.f, 0.f, 0.f);
#pragma unroll
    for (int t = 0; t < T; ++t) {
        float4 v = adj[(size_t)t * (size_t)n4 + (size_t)i];
        s.x = fmaf(w[t], v.x, s.x);
        s.y = fmaf(w[t], v.y, s.y);
        s.z = fmaf(w[t], v.z, s.z);
        s.w = fmaf(w[t], v.w, s.w);
    }
    out[i] = s;
}

// Generic-T fallback (no full unroll; still vectorized).
__global__ void __launch_bounds__(256)
ema_fold_generic(const float4* __restrict__ adj,
                 const float* __restrict__ lam_p,
                 float4* __restrict__ out,
                 int n4, int T) {
    int i = blockIdx.x * blockDim.x + threadIdx.x;
    if (i >= n4) return;

    const float lam = __ldg(lam_p);
    const float om  = 1.0f - lam;

    // Sequential recurrence on registers (T small).
    float4 s = adj[i];
    for (int t = 1; t < T; ++t) {
        float4 v = adj[(size_t)t * (size_t)n4 + (size_t)i];
        s.x = fmaf(om, s.x, lam * v.x);
        s.y = fmaf(om, s.y, lam * v.y);
        s.z = fmaf(om, s.z, lam * v.z);
        s.w = fmaf(om, s.w, lam * v.w);
    }
    out[i] = s;
}

extern "C" void kernel_launch(void* const* d_in, const int* in_sizes, int n_in,
                              void* d_out, int out_size) {
    const float4* adj  = (const float4*)d_in[0];
    const float*  lamp = (const float*)d_in[1];
    float4*       out  = (float4*)d_out;

    const int total = in_sizes[0];        // T * N * N
    const int T     = total / out_size;   // leading axis length
    const int n4    = out_size / 4;       // float4 elements per slice

    const int threads = 256;
    const int blocks  = (n4 + threads - 1) / threads;

    if (T == 16) {
        ema_fold_kernel<16><<<blocks, threads>>>(adj, lamp, out, n4);
    } else {
        ema_fold_generic<<<blocks, threads>>>(adj, lamp, out, n4, T);
    }
}

// round 2
// speedup vs baseline: 1.0099x; 1.0099x over previous
#include <cuda_runtime.h>

// out = foldl over T slices: s = (1-lam)*s + lam*adj[t], s0 = adj[0]
// Pure HBM streaming (272 MB @ T=16, N=2048). Recurrence form in registers
// (no weight array -> low regs -> full occupancy), streaming cache hints.

template <int T>
__global__ void __launch_bounds__(256, 8)
ema_fold_kernel(const float4* __restrict__ adj,
                const float* __restrict__ lam_p,
                float4* __restrict__ out,
                int n4) {
    int i = blockIdx.x * blockDim.x + threadIdx.x;
    if (i >= n4) return;

    const float lam = __ldg(lam_p);
    const float om  = 1.0f - lam;

    const float4* p = adj + i;
    float4 s = __ldcs(p);
#pragma unroll
    for (int t = 1; t < T; ++t) {
        float4 v = __ldcs(p + (size_t)t * (size_t)n4);
        s.x = fmaf(om, s.x, lam * v.x);
        s.y = fmaf(om, s.y, lam * v.y);
        s.z = fmaf(om, s.z, lam * v.z);
        s.w = fmaf(om, s.w, lam * v.w);
    }
    __stcs(out + i, s);
}

// Generic-T fallback (runtime T).
__global__ void __launch_bounds__(256, 8)
ema_fold_generic(const float4* __restrict__ adj,
                 const float* __restrict__ lam_p,
                 float4* __restrict__ out,
                 int n4, int T) {
    int i = blockIdx.x * blockDim.x + threadIdx.x;
    if (i >= n4) return;

    const float lam = __ldg(lam_p);
    const float om  = 1.0f - lam;

    const float4* p = adj + i;
    float4 s = __ldcs(p);
    for (int t = 1; t < T; ++t) {
        float4 v = __ldcs(p + (size_t)t * (size_t)n4);
        s.x = fmaf(om, s.x, lam * v.x);
        s.y = fmaf(om, s.y, lam * v.y);
        s.z = fmaf(om, s.z, lam * v.z);
        s.w = fmaf(om, s.w, lam * v.w);
    }
    __stcs(out + i, s);
}

extern "C" void kernel_launch(void* const* d_in, const int* in_sizes, int n_in,
                              void* d_out, int out_size) {
    const float4* adj  = (const float4*)d_in[0];
    const float*  lamp = (const float*)d_in[1];
    float4*       out  = (float4*)d_out;

    const int total = in_sizes[0];        // T * N * N
    const int T     = total / out_size;   // leading axis length
    const int n4    = out_size / 4;       // float4 elements per slice

    const int threads = 256;
    const int blocks  = (n4 + threads - 1) / threads;

    if (T == 16) {
        ema_fold_kernel<16><<<blocks, threads>>>(adj, lamp, out, n4);
    } else {
        ema_fold_generic<<<blocks, threads>>>(adj, lamp, out, n4, T);
    }
}